// round 12
// baseline (speedup 1.0000x reference)
#include <cuda_runtime.h>
#include <cuda_fp16.h>
#include <cstdint>

#define B_    4096
#define D_    1024
#define NI    15
#define NL    16
#define NH    256
#define NC    100
#define HC    4096
#define EPSF  1e-10f

#define TILE_M 128
#define TILE_N 128
#define KCHUNK 64
#define NITER1 (D_ / KCHUNK)            // 16
#define KSPLIT2 8
#define KCH2   (HC / KSPLIT2)           // 512
#define NITER2 (KCH2 / KCHUNK)          // 8
#define ABUF   (TILE_M * 128)
#define BBUF   (TILE_N * 128)
#define STAGE_BYTES (ABUF + BBUF)       // 32KB
#define NSTAGE 3
#define SMEM_TOTAL (NSTAGE * STAGE_BYTES) // 96KB -> 2 CTAs/SM

#define GUM_CTAS   148                  // persistent gumbel CTAs, placed first
#define GUM_CHUNKS (NI * B_ / 8)        // 7680
#define GEMM_TILES 1024                 // 32 x 32

// ---- scratch (device globals) ----
__device__ float g_split[NI * B_];
__device__ float g_p[NL * B_];
__device__ float g_part[KSPLIT2][(size_t)B_ * 128];
__device__ int   g_cnt[B_ / TILE_M];    // 32 split-K arrival counters
__device__ float g_efl[NI * D_];
__device__ float g_c1[NI * D_];
__device__ __half g_xh[(size_t)B_ * D_];
__device__ __half g_wh[(size_t)HC * D_];
__device__ __half g_hs[(size_t)B_ * HC];
__device__ __half g_w2h[(size_t)128 * HC];

// ============================================================
// helpers
// ============================================================
__device__ __forceinline__ uint32_t smem_to_u32(const void* p) {
    uint32_t a;
    asm("{ .reg .u64 t; cvta.to.shared.u64 t, %1; cvt.u32.u64 %0, t; }" : "=r"(a) : "l"(p));
    return a;
}
__device__ __forceinline__ void cp_async16(uint32_t dst, const void* src) {
    asm volatile("cp.async.cg.shared.global [%0], [%1], 16;" :: "r"(dst), "l"(src));
}
__device__ __forceinline__ void cp_commit() { asm volatile("cp.async.commit_group;"); }
template<int N> __device__ __forceinline__ void cp_wait() {
    asm volatile("cp.async.wait_group %0;" :: "n"(N));
}
__device__ __forceinline__ void ldm_x4(uint32_t& r0, uint32_t& r1, uint32_t& r2, uint32_t& r3, uint32_t addr) {
    asm volatile("ldmatrix.sync.aligned.m8n8.x4.shared.b16 {%0,%1,%2,%3}, [%4];"
                 : "=r"(r0), "=r"(r1), "=r"(r2), "=r"(r3) : "r"(addr));
}
__device__ __forceinline__ void mma_fp16(float* d, const uint32_t* a, const uint32_t* b) {
    asm volatile("mma.sync.aligned.m16n8k16.row.col.f32.f16.f16.f32 "
                 "{%0,%1,%2,%3}, {%4,%5,%6,%7}, {%8,%9}, {%0,%1,%2,%3};"
                 : "+f"(d[0]), "+f"(d[1]), "+f"(d[2]), "+f"(d[3])
                 : "r"(a[0]), "r"(a[1]), "r"(a[2]), "r"(a[3]), "r"(b[0]), "r"(b[1]));
}
__device__ __forceinline__ float frcp(float x) {
    float r;
    asm("rcp.approx.f32 %0, %1;" : "=f"(r) : "f"(x));
    return r;
}
__device__ __forceinline__ uint32_t hscale(uint32_t a, __half2 s) {
    __half2 v = __hmul2(*(__half2*)&a, s);
    return *(uint32_t*)&v;
}

// ============================================================
// Kernel 0 (prep): conversions + tables + counter reset
// ============================================================
#define N4X (B_ * D_ / 4)
#define N4W (HC * D_ / 4)
#define N4P (128 * HC / 4)
#define N4F (NI * D_ / 4)
__global__ void k_prep(const float* __restrict__ x, const float* __restrict__ w,
                       const float* __restrict__ W2,
                       const float* __restrict__ fl, const float* __restrict__ fw) {
    int i = blockIdx.x * blockDim.x + threadIdx.x;
    if (blockIdx.x == 0 && threadIdx.x < B_ / TILE_M) g_cnt[threadIdx.x] = 0;
    if (i < N4X) {
        float4 v = ((const float4*)x)[i];
        ((__half2*)g_xh)[2*i]   = __half2(__float2half_rn(v.x), __float2half_rn(v.y));
        ((__half2*)g_xh)[2*i+1] = __half2(__float2half_rn(v.z), __float2half_rn(v.w));
    } else if (i < N4X + N4W) {
        int j = i - N4X;
        float4 v = ((const float4*)w)[j];
        ((__half2*)g_wh)[2*j]   = __half2(__float2half_rn(v.x), __float2half_rn(v.y));
        ((__half2*)g_wh)[2*j+1] = __half2(__float2half_rn(v.z), __float2half_rn(v.w));
    } else if (i < N4X + N4W + N4P) {
        int j4 = i - N4X - N4W;
        int c  = j4 >> 10;
        int jj = (j4 & 1023) * 4;
        int l  = jj >> 8;
        int h  = jj & 255;
        float4 v = (c < NC) ? *(const float4*)&W2[((size_t)l * NC + c) * NH + h]
                            : make_float4(0.f, 0.f, 0.f, 0.f);
        ((__half2*)g_w2h)[(size_t)(c * HC + jj) / 2]     = __half2(__float2half_rn(v.x), __float2half_rn(v.y));
        ((__half2*)g_w2h)[(size_t)(c * HC + jj) / 2 + 1] = __half2(__float2half_rn(v.z), __float2half_rn(v.w));
    } else if (i < N4X + N4W + N4P + N4F) {
        int q = i - N4X - N4W - N4P;
        float4 f = ((const float4*)fl)[q];
        float4 w4 = ((const float4*)fw)[q];
        float4 e, c;
        e.x = __expf(f.x); e.y = __expf(f.y); e.z = __expf(f.z); e.w = __expf(f.w);
        c.x = e.x * w4.x;  c.y = e.y * w4.y;  c.z = e.z * w4.z;  c.w = e.w * w4.w;
        ((float4*)g_efl)[q] = e;
        ((float4*)g_c1)[q]  = c;
    }
}

// ============================================================
// Kernel 2: leaf routing probabilities
// ============================================================
__global__ void k_leaf_probs() {
    int b = blockIdx.x * blockDim.x + threadIdx.x;
    if (b >= B_) return;
    float s[NI];
    #pragma unroll
    for (int i = 0; i < NI; i++) s[i] = g_split[i * B_ + b];
    #pragma unroll
    for (int l = 0; l < NL; l++) {
        float p = 1.f;
        int pos = 0;
        #pragma unroll
        for (int k = 0; k < 4; k++) {
            int bit = (l >> (3 - k)) & 1;
            float sv = s[(1 << k) - 1 + pos];
            p *= bit ? sv : (1.f - sv);
            pos = 2 * pos + bit;
        }
        g_p[l * B_ + b] = p;
    }
}

// ============================================================
// shared HMMA machinery (8 warps, 64x32 warp tile)
// ============================================================
template<int LD>
__device__ __forceinline__ void stage_prefetch(uint32_t sbase, int stage,
                                               const __half* A, const __half* Bm,
                                               int m0, int n0, int k0, int tid) {
    uint32_t st = sbase + stage * STAGE_BYTES;
    int r  = tid >> 1;
    int cs = (tid & 1) * 4;
    const __half* sa = A  + (size_t)(m0 + r) * LD + k0;
    const __half* sb = Bm + (size_t)(n0 + r) * LD + k0;
    uint32_t rb_a = st + r * 128;
    uint32_t rb_b = st + ABUF + r * 128;
    #pragma unroll
    for (int c = cs; c < cs + 4; c++) {
        uint32_t phys = (uint32_t)(c ^ (r & 7)) * 16;
        cp_async16(rb_a + phys, sa + c * 8);
        cp_async16(rb_b + phys, sb + c * 8);
    }
}

// ============================================================
// fused kernel: bid < GUM_CTAS -> persistent gumbel (grid-stride)
//               else           -> GEMM1 tile
// ============================================================
__global__ void __launch_bounds__(256, 2) k_fused(const float* __restrict__ b1,
                                                  const float* __restrict__ x,
                                                  const float* __restrict__ u,
                                                  const float* __restrict__ thr) {
    extern __shared__ char smem[];
    int tid = threadIdx.x;
    int wid = tid >> 5, lane = tid & 31;

    if (blockIdx.x < GUM_CTAS) {
        // ---------------- persistent gumbel path ----------------
        for (int chunk = blockIdx.x; chunk < GUM_CHUNKS; chunk += GUM_CTAS) {
            int row = chunk * 8 + wid;
            int n = row / B_;
            int b = row - n * B_;
            const float4* u4 = (const float4*)(u + (size_t)row * D_);
            const float4* x4 = (const float4*)(x + (size_t)b   * D_);
            const float4* e4 = (const float4*)(g_efl + n * D_);
            const float4* c4 = (const float4*)(g_c1  + n * D_);

            float s0 = 0.f, s1 = 0.f;
            #pragma unroll
            for (int i = 0; i < 8; i++) {
                int idx = i * 32 + lane;
                float4 uv = u4[idx], xv = x4[idx], ev = e4[idx], cv = c4[idx];
                float r;
                r = frcp(-__logf(uv.x + EPSF) + EPSF); s0 = fmaf(ev.x, r, s0); s1 = fmaf(cv.x * xv.x, r, s1);
                r = frcp(-__logf(uv.y + EPSF) + EPSF); s0 = fmaf(ev.y, r, s0); s1 = fmaf(cv.y * xv.y, r, s1);
                r = frcp(-__logf(uv.z + EPSF) + EPSF); s0 = fmaf(ev.z, r, s0); s1 = fmaf(cv.z * xv.z, r, s1);
                r = frcp(-__logf(uv.w + EPSF) + EPSF); s0 = fmaf(ev.w, r, s0); s1 = fmaf(cv.w * xv.w, r, s1);
            }
            #pragma unroll
            for (int off = 16; off; off >>= 1) {
                s0 += __shfl_down_sync(0xffffffffu, s0, off);
                s1 += __shfl_down_sync(0xffffffffu, s1, off);
            }
            if (lane == 0) {
                float z = s1 / s0 - thr[n];
                g_split[row] = 1.f / (1.f + __expf(-z));
            }
        }
        return;
    }

    // ---------------- GEMM1 path ----------------
    uint32_t sbase = smem_to_u32(smem);
    int bid2 = blockIdx.x - GUM_CTAS;
    int m_w = (wid & 1) * 64;
    int n_w = (wid >> 1) * 32;
    int m0 = (bid2 >> 5) * TILE_M;
    int n0 = (bid2 & 31) * TILE_N;

    float acc[4][4][4] = {};

    stage_prefetch<D_>(sbase, 0, g_xh, g_wh, m0, n0, 0, tid);
    cp_commit();
    stage_prefetch<D_>(sbase, 1, g_xh, g_wh, m0, n0, KCHUNK, tid);
    cp_commit();
    stage_prefetch<D_>(sbase, 2, g_xh, g_wh, m0, n0, 2 * KCHUNK, tid);
    cp_commit();

    for (int i = 0; i < NITER1; i++) {
        int s = i % NSTAGE;
        cp_wait<2>();
        __syncthreads();

        uint32_t st = sbase + s * STAGE_BYTES;
        #pragma unroll
        for (int kk = 0; kk < 4; kk++) {
            int cbase = kk * 2;
            uint32_t ah[4][4], bh[4][2];
            #pragma unroll
            for (int mi = 0; mi < 4; mi++) {
                int r = m_w + mi * 16 + (lane & 15);
                uint32_t ch = (uint32_t)((cbase + (lane >> 4)) ^ (r & 7));
                uint32_t off = (uint32_t)r * 128 + ch * 16;
                ldm_x4(ah[mi][0], ah[mi][1], ah[mi][2], ah[mi][3], st + off);
            }
            #pragma unroll
            for (int nip = 0; nip < 2; nip++) {
                int g = lane >> 3;
                int r = n_w + (nip * 2 + (g >> 1)) * 8 + (lane & 7);
                uint32_t ch = (uint32_t)((cbase + (g & 1)) ^ (r & 7));
                uint32_t off = (uint32_t)r * 128 + ch * 16;
                ldm_x4(bh[nip*2][0], bh[nip*2][1], bh[nip*2+1][0], bh[nip*2+1][1],
                       st + ABUF + off);
            }
            #pragma unroll
            for (int mi = 0; mi < 4; mi++)
                #pragma unroll
                for (int ni = 0; ni < 4; ni++)
                    mma_fp16(acc[mi][ni], ah[mi], bh[ni]);
        }
        __syncthreads();
        if (i + NSTAGE < NITER1)
            stage_prefetch<D_>(sbase, s, g_xh, g_wh, m0, n0, (i + NSTAGE) * KCHUNK, tid);
        cp_commit();
    }

    int trow = lane >> 2;
    int tcol = (lane & 3) * 2;
    #pragma unroll
    for (int mi = 0; mi < 4; mi++) {
        int mA = m0 + m_w + mi * 16 + trow;
        int mB = mA + 8;
        #pragma unroll
        for (int ni = 0; ni < 4; ni++) {
            int n = n0 + n_w + ni * 8 + tcol;
            float bv0 = __ldg(&b1[n]), bv1 = __ldg(&b1[n + 1]);
            float v00 = fmaxf(acc[mi][ni][0] + bv0, 0.f);
            float v01 = fmaxf(acc[mi][ni][1] + bv1, 0.f);
            float v10 = fmaxf(acc[mi][ni][2] + bv0, 0.f);
            float v11 = fmaxf(acc[mi][ni][3] + bv1, 0.f);
            *(__half2*)&g_hs[(size_t)mA * HC + n] =
                __half2(__float2half_rn(v00), __float2half_rn(v01));
            *(__half2*)&g_hs[(size_t)mB * HC + n] =
                __half2(__float2half_rn(v10), __float2half_rn(v11));
        }
    }
}

// ============================================================
// GEMM2: split-K partials with p folded into A frags + fused
// deterministic last-block reduction (adds leaf-weighted b2)
// ============================================================
__global__ void __launch_bounds__(256, 2) k_gemm2(const float* __restrict__ b2,
                                                  float* __restrict__ out) {
    extern __shared__ char smem[];
    uint32_t sbase = smem_to_u32(smem);
    int tid = threadIdx.x;
    int wid = tid >> 5, lane = tid & 31;
    int m_w = (wid & 1) * 64;
    int n_w = (wid >> 1) * 32;
    int m0 = blockIdx.y * TILE_M;
    int kbase = blockIdx.x * KCH2;
    int trow = lane >> 2;

    float acc[4][4][4] = {};

    stage_prefetch<HC>(sbase, 0, g_hs, g_w2h, m0, 0, kbase, tid);
    cp_commit();
    stage_prefetch<HC>(sbase, 1, g_hs, g_w2h, m0, 0, kbase + KCHUNK, tid);
    cp_commit();
    stage_prefetch<HC>(sbase, 2, g_hs, g_w2h, m0, 0, kbase + 2 * KCHUNK, tid);
    cp_commit();

    for (int i = 0; i < NITER2; i++) {
        int s = i % NSTAGE;
        int leaf = (kbase + i * KCHUNK) >> 8;
        __half2 ph[4][2];
        #pragma unroll
        for (int mi = 0; mi < 4; mi++) {
            int mr = m0 + m_w + mi * 16 + trow;
            ph[mi][0] = __float2half2_rn(g_p[leaf * B_ + mr]);
            ph[mi][1] = __float2half2_rn(g_p[leaf * B_ + mr + 8]);
        }

        cp_wait<2>();
        __syncthreads();

        uint32_t st = sbase + s * STAGE_BYTES;
        #pragma unroll
        for (int kk = 0; kk < 4; kk++) {
            int cbase = kk * 2;
            uint32_t ah[4][4], bh[4][2];
            #pragma unroll
            for (int mi = 0; mi < 4; mi++) {
                int r = m_w + mi * 16 + (lane & 15);
                uint32_t ch = (uint32_t)((cbase + (lane >> 4)) ^ (r & 7));
                uint32_t off = (uint32_t)r * 128 + ch * 16;
                ldm_x4(ah[mi][0], ah[mi][1], ah[mi][2], ah[mi][3], st + off);
                ah[mi][0] = hscale(ah[mi][0], ph[mi][0]);
                ah[mi][1] = hscale(ah[mi][1], ph[mi][1]);
                ah[mi][2] = hscale(ah[mi][2], ph[mi][0]);
                ah[mi][3] = hscale(ah[mi][3], ph[mi][1]);
            }
            #pragma unroll
            for (int nip = 0; nip < 2; nip++) {
                int g = lane >> 3;
                int r = n_w + (nip * 2 + (g >> 1)) * 8 + (lane & 7);
                uint32_t ch = (uint32_t)((cbase + (g & 1)) ^ (r & 7));
                uint32_t off = (uint32_t)r * 128 + ch * 16;
                ldm_x4(bh[nip*2][0], bh[nip*2][1], bh[nip*2+1][0], bh[nip*2+1][1],
                       st + ABUF + off);
            }
            #pragma unroll
            for (int mi = 0; mi < 4; mi++)
                #pragma unroll
                for (int ni = 0; ni < 4; ni++)
                    mma_fp16(acc[mi][ni], ah[mi], bh[ni]);
        }
        __syncthreads();
        if (i + NSTAGE < NITER2)
            stage_prefetch<HC>(sbase, s, g_hs, g_w2h, m0, 0, kbase + (i + NSTAGE) * KCHUNK, tid);
        cp_commit();
    }

    int tcol = (lane & 3) * 2;
    float* part = g_part[blockIdx.x];
    #pragma unroll
    for (int mi = 0; mi < 4; mi++) {
        int mA = m0 + m_w + mi * 16 + trow;
        int mB = mA + 8;
        #pragma unroll
        for (int ni = 0; ni < 4; ni++) {
            int n = n_w + ni * 8 + tcol;
            *(float2*)&part[(size_t)mA * 128 + n] = make_float2(acc[mi][ni][0], acc[mi][ni][1]);
            *(float2*)&part[(size_t)mB * 128 + n] = make_float2(acc[mi][ni][2], acc[mi][ni][3]);
        }
    }

    // ---- deterministic last-block reduction for this m-block ----
    __threadfence();
    __shared__ int done;
    if (tid == 0) done = atomicAdd(&g_cnt[blockIdx.y], 1);
    __syncthreads();
    if (done == KSPLIT2 - 1) {
        for (int idx = tid; idx < TILE_M * NC; idx += 256) {
            int r = idx / NC;
            int c = idx - r * NC;
            int b = m0 + r;
            float v = 0.f;
            #pragma unroll
            for (int s = 0; s < KSPLIT2; s++) v += g_part[s][(size_t)b * 128 + c];
            float bias = 0.f;
            #pragma unroll
            for (int l = 0; l < NL; l++) bias += g_p[l * B_ + b] * b2[l * NC + c];
            out[(size_t)b * NC + c] = v + bias;
        }
    }
}

extern "C" void kernel_launch(void* const* d_in, const int* in_sizes, int n_in,
                              void* d_out, int out_size) {
    const float* x   = (const float*)d_in[0];
    const float* u   = (const float*)d_in[1];
    const float* fl  = (const float*)d_in[2];
    const float* thr = (const float*)d_in[3];
    const float* fw  = (const float*)d_in[4];
    const float* W1  = (const float*)d_in[5];
    const float* b1  = (const float*)d_in[6];
    const float* W2  = (const float*)d_in[7];
    const float* b2  = (const float*)d_in[8];
    float* out = (float*)d_out;

    cudaFuncSetAttribute(k_fused, cudaFuncAttributeMaxDynamicSharedMemorySize, SMEM_TOTAL);
    cudaFuncSetAttribute(k_gemm2, cudaFuncAttributeMaxDynamicSharedMemorySize, SMEM_TOTAL);

    k_prep<<<(N4X + N4W + N4P + N4F + 255) / 256, 256>>>(x, W1, W2, fl, fw);
    k_fused<<<GUM_CTAS + GEMM_TILES, 256, SMEM_TOTAL>>>(b1, x, u, thr);
    k_leaf_probs<<<B_ / 128, 128>>>();
    k_gemm2<<<dim3(KSPLIT2, B_ / TILE_M), 256, SMEM_TOTAL>>>(b2, out);
}

// round 13
// speedup vs baseline: 1.1166x; 1.1166x over previous
#include <cuda_runtime.h>
#include <cuda_fp16.h>
#include <cstdint>

#define B_    4096
#define D_    1024
#define NI    15
#define NL    16
#define NH    256
#define NC    100
#define HC    4096
#define EPSF  1e-10f

#define TILE_M 128
#define TILE_N 128
#define KCHUNK 64
#define NITER1 (D_ / KCHUNK)            // 16
#define KSPLIT2 8
#define KCH2   (HC / KSPLIT2)           // 512
#define NITER2 (KCH2 / KCHUNK)          // 8
#define ABUF   (TILE_M * 128)
#define BBUF   (TILE_N * 128)
#define STAGE_BYTES (ABUF + BBUF)       // 32KB
#define NSTAGE 3
#define SMEM_TOTAL (NSTAGE * STAGE_BYTES) // 96KB dynamic

#define GUM_CTAS   148
#define GUM_CHUNKS (NI * B_ / 8)        // 7680
#define GEMM_TILES 1024                 // 32 x 32

// ---- scratch (device globals) ----
__device__ float g_split[NI * B_];
__device__ float g_part[KSPLIT2][(size_t)B_ * 128];
__device__ int   g_cnt[B_ / TILE_M];    // 32 split-K arrival counters
__device__ float g_efl[NI * D_];
__device__ float g_c1[NI * D_];
__device__ __half g_xh[(size_t)B_ * D_];
__device__ __half g_wh[(size_t)HC * D_];
__device__ __half g_hs[(size_t)B_ * HC];
__device__ __half g_w2h[(size_t)128 * HC];

// ============================================================
// helpers
// ============================================================
__device__ __forceinline__ uint32_t smem_to_u32(const void* p) {
    uint32_t a;
    asm("{ .reg .u64 t; cvta.to.shared.u64 t, %1; cvt.u32.u64 %0, t; }" : "=r"(a) : "l"(p));
    return a;
}
__device__ __forceinline__ void cp_async16(uint32_t dst, const void* src) {
    asm volatile("cp.async.cg.shared.global [%0], [%1], 16;" :: "r"(dst), "l"(src));
}
__device__ __forceinline__ void cp_commit() { asm volatile("cp.async.commit_group;"); }
template<int N> __device__ __forceinline__ void cp_wait() {
    asm volatile("cp.async.wait_group %0;" :: "n"(N));
}
__device__ __forceinline__ void ldm_x4(uint32_t& r0, uint32_t& r1, uint32_t& r2, uint32_t& r3, uint32_t addr) {
    asm volatile("ldmatrix.sync.aligned.m8n8.x4.shared.b16 {%0,%1,%2,%3}, [%4];"
                 : "=r"(r0), "=r"(r1), "=r"(r2), "=r"(r3) : "r"(addr));
}
__device__ __forceinline__ void mma_fp16(float* d, const uint32_t* a, const uint32_t* b) {
    asm volatile("mma.sync.aligned.m16n8k16.row.col.f32.f16.f16.f32 "
                 "{%0,%1,%2,%3}, {%4,%5,%6,%7}, {%8,%9}, {%0,%1,%2,%3};"
                 : "+f"(d[0]), "+f"(d[1]), "+f"(d[2]), "+f"(d[3])
                 : "r"(a[0]), "r"(a[1]), "r"(a[2]), "r"(a[3]), "r"(b[0]), "r"(b[1]));
}
__device__ __forceinline__ float frcp(float x) {
    float r;
    asm("rcp.approx.f32 %0, %1;" : "=f"(r) : "f"(x));
    return r;
}
__device__ __forceinline__ uint32_t hscale(uint32_t a, __half2 s) {
    __half2 v = __hmul2(*(__half2*)&a, s);
    return *(uint32_t*)&v;
}

// ============================================================
// Kernel 0 (prep): conversions + tables + counter reset
// ============================================================
#define N4X (B_ * D_ / 4)
#define N4W (HC * D_ / 4)
#define N4P (128 * HC / 4)
#define N4F (NI * D_ / 4)
__global__ void k_prep(const float* __restrict__ x, const float* __restrict__ w,
                       const float* __restrict__ W2,
                       const float* __restrict__ fl, const float* __restrict__ fw) {
    int i = blockIdx.x * blockDim.x + threadIdx.x;
    if (blockIdx.x == 0 && threadIdx.x < B_ / TILE_M) g_cnt[threadIdx.x] = 0;
    if (i < N4X) {
        float4 v = ((const float4*)x)[i];
        ((__half2*)g_xh)[2*i]   = __half2(__float2half_rn(v.x), __float2half_rn(v.y));
        ((__half2*)g_xh)[2*i+1] = __half2(__float2half_rn(v.z), __float2half_rn(v.w));
    } else if (i < N4X + N4W) {
        int j = i - N4X;
        float4 v = ((const float4*)w)[j];
        ((__half2*)g_wh)[2*j]   = __half2(__float2half_rn(v.x), __float2half_rn(v.y));
        ((__half2*)g_wh)[2*j+1] = __half2(__float2half_rn(v.z), __float2half_rn(v.w));
    } else if (i < N4X + N4W + N4P) {
        int j4 = i - N4X - N4W;
        int c  = j4 >> 10;
        int jj = (j4 & 1023) * 4;
        int l  = jj >> 8;
        int h  = jj & 255;
        float4 v = (c < NC) ? *(const float4*)&W2[((size_t)l * NC + c) * NH + h]
                            : make_float4(0.f, 0.f, 0.f, 0.f);
        ((__half2*)g_w2h)[(size_t)(c * HC + jj) / 2]     = __half2(__float2half_rn(v.x), __float2half_rn(v.y));
        ((__half2*)g_w2h)[(size_t)(c * HC + jj) / 2 + 1] = __half2(__float2half_rn(v.z), __float2half_rn(v.w));
    } else if (i < N4X + N4W + N4P + N4F) {
        int q = i - N4X - N4W - N4P;
        float4 f = ((const float4*)fl)[q];
        float4 w4 = ((const float4*)fw)[q];
        float4 e, c;
        e.x = __expf(f.x); e.y = __expf(f.y); e.z = __expf(f.z); e.w = __expf(f.w);
        c.x = e.x * w4.x;  c.y = e.y * w4.y;  c.z = e.z * w4.z;  c.w = e.w * w4.w;
        ((float4*)g_efl)[q] = e;
        ((float4*)g_c1)[q]  = c;
    }
}

// ============================================================
// shared HMMA machinery (8 warps, 64x32 warp tile)
// ============================================================
template<int LD>
__device__ __forceinline__ void stage_prefetch(uint32_t sbase, int stage,
                                               const __half* A, const __half* Bm,
                                               int m0, int n0, int k0, int tid) {
    uint32_t st = sbase + stage * STAGE_BYTES;
    int r  = tid >> 1;
    int cs = (tid & 1) * 4;
    const __half* sa = A  + (size_t)(m0 + r) * LD + k0;
    const __half* sb = Bm + (size_t)(n0 + r) * LD + k0;
    uint32_t rb_a = st + r * 128;
    uint32_t rb_b = st + ABUF + r * 128;
    #pragma unroll
    for (int c = cs; c < cs + 4; c++) {
        uint32_t phys = (uint32_t)(c ^ (r & 7)) * 16;
        cp_async16(rb_a + phys, sa + c * 8);
        cp_async16(rb_b + phys, sb + c * 8);
    }
}

// ============================================================
// fused kernel: bid < GUM_CTAS -> persistent gumbel (grid-stride)
//               else           -> GEMM1 tile
// ============================================================
__global__ void __launch_bounds__(256, 2) k_fused(const float* __restrict__ b1,
                                                  const float* __restrict__ x,
                                                  const float* __restrict__ u,
                                                  const float* __restrict__ thr) {
    extern __shared__ char smem[];
    int tid = threadIdx.x;
    int wid = tid >> 5, lane = tid & 31;

    if (blockIdx.x < GUM_CTAS) {
        for (int chunk = blockIdx.x; chunk < GUM_CHUNKS; chunk += GUM_CTAS) {
            int row = chunk * 8 + wid;
            int n = row / B_;
            int b = row - n * B_;
            const float4* u4 = (const float4*)(u + (size_t)row * D_);
            const float4* x4 = (const float4*)(x + (size_t)b   * D_);
            const float4* e4 = (const float4*)(g_efl + n * D_);
            const float4* c4 = (const float4*)(g_c1  + n * D_);

            float s0 = 0.f, s1 = 0.f;
            #pragma unroll
            for (int i = 0; i < 8; i++) {
                int idx = i * 32 + lane;
                float4 uv = u4[idx], xv = x4[idx], ev = e4[idx], cv = c4[idx];
                float r;
                r = frcp(-__logf(uv.x + EPSF) + EPSF); s0 = fmaf(ev.x, r, s0); s1 = fmaf(cv.x * xv.x, r, s1);
                r = frcp(-__logf(uv.y + EPSF) + EPSF); s0 = fmaf(ev.y, r, s0); s1 = fmaf(cv.y * xv.y, r, s1);
                r = frcp(-__logf(uv.z + EPSF) + EPSF); s0 = fmaf(ev.z, r, s0); s1 = fmaf(cv.z * xv.z, r, s1);
                r = frcp(-__logf(uv.w + EPSF) + EPSF); s0 = fmaf(ev.w, r, s0); s1 = fmaf(cv.w * xv.w, r, s1);
            }
            #pragma unroll
            for (int off = 16; off; off >>= 1) {
                s0 += __shfl_down_sync(0xffffffffu, s0, off);
                s1 += __shfl_down_sync(0xffffffffu, s1, off);
            }
            if (lane == 0) {
                float z = s1 / s0 - thr[n];
                g_split[row] = 1.f / (1.f + __expf(-z));
            }
        }
        return;
    }

    // ---------------- GEMM1 path ----------------
    uint32_t sbase = smem_to_u32(smem);
    int bid2 = blockIdx.x - GUM_CTAS;
    int m_w = (wid & 1) * 64;
    int n_w = (wid >> 1) * 32;
    int m0 = (bid2 >> 5) * TILE_M;
    int n0 = (bid2 & 31) * TILE_N;

    float acc[4][4][4] = {};

    stage_prefetch<D_>(sbase, 0, g_xh, g_wh, m0, n0, 0, tid);
    cp_commit();
    stage_prefetch<D_>(sbase, 1, g_xh, g_wh, m0, n0, KCHUNK, tid);
    cp_commit();
    stage_prefetch<D_>(sbase, 2, g_xh, g_wh, m0, n0, 2 * KCHUNK, tid);
    cp_commit();

    for (int i = 0; i < NITER1; i++) {
        int s = i % NSTAGE;
        cp_wait<2>();
        __syncthreads();

        uint32_t st = sbase + s * STAGE_BYTES;
        #pragma unroll
        for (int kk = 0; kk < 4; kk++) {
            int cbase = kk * 2;
            uint32_t ah[4][4], bh[4][2];
            #pragma unroll
            for (int mi = 0; mi < 4; mi++) {
                int r = m_w + mi * 16 + (lane & 15);
                uint32_t ch = (uint32_t)((cbase + (lane >> 4)) ^ (r & 7));
                uint32_t off = (uint32_t)r * 128 + ch * 16;
                ldm_x4(ah[mi][0], ah[mi][1], ah[mi][2], ah[mi][3], st + off);
            }
            #pragma unroll
            for (int nip = 0; nip < 2; nip++) {
                int g = lane >> 3;
                int r = n_w + (nip * 2 + (g >> 1)) * 8 + (lane & 7);
                uint32_t ch = (uint32_t)((cbase + (g & 1)) ^ (r & 7));
                uint32_t off = (uint32_t)r * 128 + ch * 16;
                ldm_x4(bh[nip*2][0], bh[nip*2][1], bh[nip*2+1][0], bh[nip*2+1][1],
                       st + ABUF + off);
            }
            #pragma unroll
            for (int mi = 0; mi < 4; mi++)
                #pragma unroll
                for (int ni = 0; ni < 4; ni++)
                    mma_fp16(acc[mi][ni], ah[mi], bh[ni]);
        }
        __syncthreads();
        if (i + NSTAGE < NITER1)
            stage_prefetch<D_>(sbase, s, g_xh, g_wh, m0, n0, (i + NSTAGE) * KCHUNK, tid);
        cp_commit();
    }

    int trow = lane >> 2;
    int tcol = (lane & 3) * 2;
    #pragma unroll
    for (int mi = 0; mi < 4; mi++) {
        int mA = m0 + m_w + mi * 16 + trow;
        int mB = mA + 8;
        #pragma unroll
        for (int ni = 0; ni < 4; ni++) {
            int n = n0 + n_w + ni * 8 + tcol;
            float bv0 = __ldg(&b1[n]), bv1 = __ldg(&b1[n + 1]);
            float v00 = fmaxf(acc[mi][ni][0] + bv0, 0.f);
            float v01 = fmaxf(acc[mi][ni][1] + bv1, 0.f);
            float v10 = fmaxf(acc[mi][ni][2] + bv0, 0.f);
            float v11 = fmaxf(acc[mi][ni][3] + bv1, 0.f);
            *(__half2*)&g_hs[(size_t)mA * HC + n] =
                __half2(__float2half_rn(v00), __float2half_rn(v01));
            *(__half2*)&g_hs[(size_t)mB * HC + n] =
                __half2(__float2half_rn(v10), __float2half_rn(v11));
        }
    }
}

// ============================================================
// GEMM2: split-K with p folded into A frags (p computed in-kernel
// from g_split) + cooperative spin-wait reduction (all 8 split CTAs
// per m-block each reduce a 13-column slice). Deterministic order.
// ============================================================
__global__ void __launch_bounds__(256, 2) k_gemm2(const float* __restrict__ b2,
                                                  float* __restrict__ out) {
    extern __shared__ char smem[];
    __shared__ float sp[NL][TILE_M];    // 8KB static: leaf probs for this m-block
    uint32_t sbase = smem_to_u32(smem);
    int tid = threadIdx.x;
    int wid = tid >> 5, lane = tid & 31;
    int m_w = (wid & 1) * 64;
    int n_w = (wid >> 1) * 32;
    int m0 = blockIdx.y * TILE_M;
    int kbase = blockIdx.x * KCH2;
    int trow = lane >> 2;

    // ---- compute leaf probs for rows m0..m0+127 into smem ----
    if (tid < TILE_M) {
        int b = m0 + tid;
        float s[NI];
        #pragma unroll
        for (int i = 0; i < NI; i++) s[i] = g_split[i * B_ + b];
        #pragma unroll
        for (int l = 0; l < NL; l++) {
            float p = 1.f;
            int pos = 0;
            #pragma unroll
            for (int k = 0; k < 4; k++) {
                int bit = (l >> (3 - k)) & 1;
                float sv = s[(1 << k) - 1 + pos];
                p *= bit ? sv : (1.f - sv);
                pos = 2 * pos + bit;
            }
            sp[l][tid] = p;
        }
    }

    float acc[4][4][4] = {};

    stage_prefetch<HC>(sbase, 0, g_hs, g_w2h, m0, 0, kbase, tid);
    cp_commit();
    stage_prefetch<HC>(sbase, 1, g_hs, g_w2h, m0, 0, kbase + KCHUNK, tid);
    cp_commit();
    stage_prefetch<HC>(sbase, 2, g_hs, g_w2h, m0, 0, kbase + 2 * KCHUNK, tid);
    cp_commit();
    __syncthreads();   // sp ready (also covered by first mainloop sync)

    for (int i = 0; i < NITER2; i++) {
        int s = i % NSTAGE;
        int leaf = (kbase + i * KCHUNK) >> 8;
        __half2 ph[4][2];
        #pragma unroll
        for (int mi = 0; mi < 4; mi++) {
            int rl = m_w + mi * 16 + trow;
            ph[mi][0] = __float2half2_rn(sp[leaf][rl]);
            ph[mi][1] = __float2half2_rn(sp[leaf][rl + 8]);
        }

        cp_wait<2>();
        __syncthreads();

        uint32_t st = sbase + s * STAGE_BYTES;
        #pragma unroll
        for (int kk = 0; kk < 4; kk++) {
            int cbase = kk * 2;
            uint32_t ah[4][4], bh[4][2];
            #pragma unroll
            for (int mi = 0; mi < 4; mi++) {
                int r = m_w + mi * 16 + (lane & 15);
                uint32_t ch = (uint32_t)((cbase + (lane >> 4)) ^ (r & 7));
                uint32_t off = (uint32_t)r * 128 + ch * 16;
                ldm_x4(ah[mi][0], ah[mi][1], ah[mi][2], ah[mi][3], st + off);
                ah[mi][0] = hscale(ah[mi][0], ph[mi][0]);
                ah[mi][1] = hscale(ah[mi][1], ph[mi][1]);
                ah[mi][2] = hscale(ah[mi][2], ph[mi][0]);
                ah[mi][3] = hscale(ah[mi][3], ph[mi][1]);
            }
            #pragma unroll
            for (int nip = 0; nip < 2; nip++) {
                int g = lane >> 3;
                int r = n_w + (nip * 2 + (g >> 1)) * 8 + (lane & 7);
                uint32_t ch = (uint32_t)((cbase + (g & 1)) ^ (r & 7));
                uint32_t off = (uint32_t)r * 128 + ch * 16;
                ldm_x4(bh[nip*2][0], bh[nip*2][1], bh[nip*2+1][0], bh[nip*2+1][1],
                       st + ABUF + off);
            }
            #pragma unroll
            for (int mi = 0; mi < 4; mi++)
                #pragma unroll
                for (int ni = 0; ni < 4; ni++)
                    mma_fp16(acc[mi][ni], ah[mi], bh[ni]);
        }
        __syncthreads();
        if (i + NSTAGE < NITER2)
            stage_prefetch<HC>(sbase, s, g_hs, g_w2h, m0, 0, kbase + (i + NSTAGE) * KCHUNK, tid);
        cp_commit();
    }

    int tcol = (lane & 3) * 2;
    float* part = g_part[blockIdx.x];
    #pragma unroll
    for (int mi = 0; mi < 4; mi++) {
        int mA = m0 + m_w + mi * 16 + trow;
        int mB = mA + 8;
        #pragma unroll
        for (int ni = 0; ni < 4; ni++) {
            int n = n_w + ni * 8 + tcol;
            *(float2*)&part[(size_t)mA * 128 + n] = make_float2(acc[mi][ni][0], acc[mi][ni][1]);
            *(float2*)&part[(size_t)mB * 128 + n] = make_float2(acc[mi][ni][2], acc[mi][ni][3]);
        }
    }

    // ---- cooperative reduction: all 8 split CTAs spin, then each
    //      reduces its own 13-column slice (deterministic order) ----
    __threadfence();
    if (tid == 0) {
        atomicAdd(&g_cnt[blockIdx.y], 1);
        while (((volatile int*)g_cnt)[blockIdx.y] < KSPLIT2) __nanosleep(64);
    }
    __syncthreads();
    __threadfence();

    int c0 = blockIdx.x * 13;
    int c1 = min(c0 + 13, NC);
    int ncols = c1 - c0;
    for (int idx = tid; idx < TILE_M * ncols; idx += 256) {
        int r = idx / ncols;
        int c = c0 + idx - r * ncols;
        int b = m0 + r;
        float v = 0.f;
        #pragma unroll
        for (int s = 0; s < KSPLIT2; s++) v += g_part[s][(size_t)b * 128 + c];
        float bias = 0.f;
        #pragma unroll
        for (int l = 0; l < NL; l++) bias += sp[l][r] * b2[l * NC + c];
        out[(size_t)b * NC + c] = v + bias;
    }
}

extern "C" void kernel_launch(void* const* d_in, const int* in_sizes, int n_in,
                              void* d_out, int out_size) {
    const float* x   = (const float*)d_in[0];
    const float* u   = (const float*)d_in[1];
    const float* fl  = (const float*)d_in[2];
    const float* thr = (const float*)d_in[3];
    const float* fw  = (const float*)d_in[4];
    const float* W1  = (const float*)d_in[5];
    const float* b1  = (const float*)d_in[6];
    const float* W2  = (const float*)d_in[7];
    const float* b2  = (const float*)d_in[8];
    float* out = (float*)d_out;

    cudaFuncSetAttribute(k_fused, cudaFuncAttributeMaxDynamicSharedMemorySize, SMEM_TOTAL);
    cudaFuncSetAttribute(k_gemm2, cudaFuncAttributeMaxDynamicSharedMemorySize, SMEM_TOTAL);

    k_prep<<<(N4X + N4W + N4P + N4F + 255) / 256, 256>>>(x, W1, W2, fl, fw);
    k_fused<<<GUM_CTAS + GEMM_TILES, 256, SMEM_TOTAL>>>(b1, x, u, thr);
    k_gemm2<<<dim3(KSPLIT2, B_ / TILE_M), 256, SMEM_TOTAL>>>(b2, out);
}